// round 4
// baseline (speedup 1.0000x reference)
#include <cuda_runtime.h>
#include <cstdint>

// Problem shape (fixed by setup_inputs): B=256, T=512, C=1024, L=64, S=129
#define Bv 256
#define Tv 512
#define Cv 1024
#define Lv 64
#define EPS 1e-7f
#define BOOST 100         // rescale target: warp max -> 2^BOOST (underflow margin)
#define CHUNK 64          // DP steps per pipeline phase
#define NCH (Tv / CHUNK)  // 8 phases
#define ROWF 66           // smem row stride (floats): 64 labels + blank + pad (8B align)

// Plain global load (avoid LDG.E.CONSTANT / 128B L2 promotion; hypothesis:
// plain path fills L2 at 32B sector granularity -> ~2.2x fewer DRAM bytes).
__device__ __forceinline__ float ldg_plain(const float* p) {
    float v;
    asm("ld.global.b32 %0, [%1];" : "=f"(v) : "l"(p));
    return v;
}

// ---------------------------------------------------------------------------
// Warp-specialized fused CTC forward. One CTA (8 warps) per batch row.
//   warps 0-6: loaders. For each 64-step chunk they gather y_pred at the 64
//     label columns + blank into a 2-chunk smem ring (fully independent loads
//     -> ~19 outstanding LDG per thread, ~385 per CTA: saturates DRAM).
//   warp 7: DP. Lane l owns states {4l..4l+3}; lane 31 also owns state 128.
//     Even states are blank (no s-2 skip), so ONE shfl_up per step suffices.
//     Linear-domain recurrence + exact power-of-2 rescale (exponent surgery,
//     warp-max pipelined over a 4-step period, off the critical path).
// Pipeline: phase p: loaders fill chunk p, DP consumes chunk p-1, then
// __syncthreads() (drains STS -> chunk p visible next phase).
// ---------------------------------------------------------------------------
__global__ void __launch_bounds__(256) ctc_ws_kernel(const int* __restrict__ y_true,
                                                     const float* __restrict__ y_pred,
                                                     float* __restrict__ out) {
    __shared__ float sm[2][CHUNK][ROWF];
    __shared__ int   lab_sm[Lv];

    int b   = blockIdx.x;
    int tid = threadIdx.x;
    int wid = tid >> 5;
    int l   = tid & 31;

    if (tid < Lv) lab_sm[tid] = y_true[b * Lv + tid];
    __syncthreads();

    const float* base = y_pred + (size_t)b * Tv * Cv;

    if (wid < 7) {
        // ---------------- loader warps ----------------
        int q = wid * 32 + l;                      // 0..223
        for (int p = 0; p <= NCH; p++) {
            if (p < NCH) {
                int buf = p & 1;
                int t0  = p * CHUNK;
                // 64 steps x 65 values = 4160 tasks, strided by 224 threads
                for (int k = q; k < CHUNK * 65; k += 224) {
                    int tl  = k / 65;
                    int j   = k - tl * 65;
                    int col = (j < 64) ? lab_sm[j] : (Cv - 1);   // blank = last class
                    float v = ldg_plain(base + (size_t)(t0 + tl) * Cv + col);
                    sm[buf][tl][j] = v + EPS;
                }
            }
            __syncthreads();
        }
    } else {
        // ---------------- DP warp ----------------
        int c0  = lab_sm[2 * l];
        int c1  = lab_sm[2 * l + 1];
        int cm1 = __shfl_up_sync(0xffffffffu, c1, 1);
        bool al1 = (l > 0) && (c0 != cm1);   // skip into state 4l+1
        bool al3 = (c1 != c0);               // skip into state 4l+3

        float a0 = 0.f, a1 = 0.f, a2 = 0.f, a3 = 0.f, a4 = 0.f;
        float r  = 1.0f;
        int   esc = 0;   // alpha_true = a * 2^esc (identical on all lanes)

        for (int p = 0; p <= NCH; p++) {
            if (p >= 1) {
                int c   = p - 1;
                int buf = c & 1;
                // one-step lookahead from smem (covers ~29cyc LDS latency)
                float2 pv  = *(const float2*)&sm[buf][0][2 * l];
                float  pbv = sm[buf][0][64];
#pragma unroll 8
                for (int tl = 0; tl < CHUNK; tl++) {
                    float px = pv.x + 0.f, py = pv.y, pb = pbv;
                    if (tl < CHUNK - 1) {
                        pv  = *(const float2*)&sm[buf][tl + 1][2 * l];
                        pbv = sm[buf][tl + 1][64];
                    }
                    int t = c * CHUNK + tl;
                    if (t == 0) {
                        if (l == 0) { a0 = pb; a1 = px; }
                    } else {
                        float pa3 = __shfl_up_sync(0xffffffffu, a3, 1);
                        if (l == 0) pa3 = 0.f;
                        float n0 = (a0 + pa3) * pb;                        // s=4l (blank)
                        float n1 = (a1 + a0 + (al1 ? pa3 : 0.f)) * px;     // s=4l+1
                        float n2 = (a2 + a1) * pb;                         // s=4l+2 (blank)
                        float n3 = (a3 + a2 + (al3 ? a1 : 0.f)) * py;      // s=4l+3
                        float n4 = (l == 31) ? (a4 + a3) * pb : 0.f;       // s=128 (blank)
                        a0 = n0; a1 = n1; a2 = n2; a3 = n3; a4 = n4;
                    }
                    // pipelined warp-max + exact 2^k rescale (period 4)
                    int ph = t & 3;
                    if (ph == 0) {
                        r = fmaxf(fmaxf(a0, a1), fmaxf(a2, a3));
                        if (l == 31) r = fmaxf(r, a4);
                        r = fmaxf(r, __shfl_xor_sync(0xffffffffu, r, 1));
                    } else if (ph == 1) {
                        r = fmaxf(r, __shfl_xor_sync(0xffffffffu, r, 2));
                        r = fmaxf(r, __shfl_xor_sync(0xffffffffu, r, 4));
                    } else if (ph == 2) {
                        r = fmaxf(r, __shfl_xor_sync(0xffffffffu, r, 8));
                        r = fmaxf(r, __shfl_xor_sync(0xffffffffu, r, 16));
                    } else {
                        int eb = (__float_as_int(r) >> 23) & 0xff;
                        int se = 254 - eb + BOOST;        // target: max -> 2^BOOST
                        se = se > 254 ? 254 : se;
                        float sc = __int_as_float(se << 23);  // exact 2^(se-127)
                        a0 *= sc; a1 *= sc; a2 *= sc; a3 *= sc; a4 *= sc;
                        esc += 127 - se;
                    }
                }
            }
            __syncthreads();
        }

        // ll = 64 -> loss from states 128 (a4) and 127 (a3), lane 31
        if (l == 31) {
            float s = a4 + a3;
            out[b] = -(logf(s) + (float)esc * 0.69314718055994531f);
        }
    }
}

extern "C" void kernel_launch(void* const* d_in, const int* in_sizes, int n_in,
                              void* d_out, int out_size) {
    const int*   y_true = (const int*)d_in[0];    // [256, 64] int32
    const float* y_pred = (const float*)d_in[1];  // [256, 512, 1024] float32
    float*       out    = (float*)d_out;          // [256, 1] float32

    ctc_ws_kernel<<<Bv, 256>>>(y_true, y_pred, out);
}

// round 7
// speedup vs baseline: 1.1004x; 1.1004x over previous
#include <cuda_runtime.h>
#include <cstdint>

// Problem shape (fixed by setup_inputs): B=256, T=512, C=1024, L=64, S=129
#define Bv 256
#define Tv 512
#define Cv 1024
#define Lv 64
#define EPS 1e-7f
#define BOOST 100         // rescale target: warp max -> 2^BOOST (underflow margin)
#define CHUNK 64          // DP steps per pipeline phase
#define NCH (Tv / CHUNK)  // 8 phases
#define ROWF 66           // smem row stride (floats): 64 labels + blank + pad

__device__ __forceinline__ void cpasync4(uint32_t smem_dst, const float* gsrc) {
    asm volatile("cp.async.ca.shared.global [%0], [%1], 4;"
                 :: "r"(smem_dst), "l"(gsrc));
}

// ---------------------------------------------------------------------------
// Warp-specialized fused CTC forward, cp.async edition. One CTA (8 warps)/row.
//   warps 0-6: loaders. Each phase gathers a 64-step chunk of y_pred at the 64
//     label columns + blank into a 2-chunk smem ring, using 4B cp.async
//     (LDGSTS: no LDG->STS register dependency -> thousands of in-flight
//     sector requests per CTA; this is what R4's plain-LDG loaders lacked).
//   warp 7: DP. Lane l owns states {4l..4l+3}; lane 31 also owns state 128.
//     Even states are blank (no s-2 skip) -> ONE shfl_up per step.
//     Linear-domain recurrence + exact power-of-2 rescale (exponent surgery,
//     warp-max pipelined over a 4-step period, off the critical path).
// Phase p: loaders issue chunk p (async), wait chunk p-1, barrier; DP consumes
// chunk p-1; barrier (so chunk p+1 can't overwrite the buffer being read).
// ---------------------------------------------------------------------------
__global__ void __launch_bounds__(256) ctc_cp_kernel(const int* __restrict__ y_true,
                                                     const float* __restrict__ y_pred,
                                                     float* __restrict__ out) {
    __shared__ float sm[2][CHUNK][ROWF];
    __shared__ int   lab_sm[Lv];

    int b   = blockIdx.x;
    int tid = threadIdx.x;
    int wid = tid >> 5;
    int l   = tid & 31;

    if (tid < Lv) lab_sm[tid] = y_true[b * Lv + tid];
    __syncthreads();

    const float* base = y_pred + (size_t)b * Tv * Cv;

    if (wid < 7) {
        // ---------------- loader warps (cp.async) ----------------
        int lab0 = lab_sm[l];
        int lab1 = lab_sm[32 + l];
        for (int p = 0; p <= NCH; p++) {
            if (p < NCH) {
                int buf = p & 1;
                int t0  = p * CHUNK;
                for (int tl = wid; tl < CHUNK; tl += 7) {
                    const float* rp = base + (size_t)(t0 + tl) * Cv;
                    uint32_t srow = (uint32_t)__cvta_generic_to_shared(&sm[buf][tl][0]);
                    cpasync4(srow + 4u * l,        rp + lab0);
                    cpasync4(srow + 4u * (32 + l), rp + lab1);
                    if (l == 0) cpasync4(srow + 4u * 64, rp + (Cv - 1)); // blank
                }
                asm volatile("cp.async.commit_group;");
                asm volatile("cp.async.wait_group 1;");   // chunk p-1 landed
            } else {
                asm volatile("cp.async.wait_group 0;");   // last chunk landed
            }
            __syncthreads();   // b1: chunk p-1 visible to DP
            __syncthreads();   // b2: DP done with chunk p-1; next buf reusable
        }
    } else {
        // ---------------- DP warp ----------------
        int c0  = lab_sm[2 * l];
        int c1  = lab_sm[2 * l + 1];
        int cm1 = __shfl_up_sync(0xffffffffu, c1, 1);
        bool al1 = (l > 0) && (c0 != cm1);   // skip into state 4l+1
        bool al3 = (c1 != c0);               // skip into state 4l+3

        float a0 = 0.f, a1 = 0.f, a2 = 0.f, a3 = 0.f, a4 = 0.f;
        float r  = 1.0f;
        int   esc = 0;   // alpha_true = a * 2^esc (identical on all lanes)

        for (int p = 0; p <= NCH; p++) {
            __syncthreads();   // b1: chunk p-1 ready
            if (p >= 1) {
                int c   = p - 1;
                int buf = c & 1;
                // one-step lookahead from smem (covers ~29cyc LDS latency)
                float2 pv  = *(const float2*)&sm[buf][0][2 * l];
                float  pbv = sm[buf][0][64];
#pragma unroll 8
                for (int tl = 0; tl < CHUNK; tl++) {
                    float px = pv.x + EPS;
                    float py = pv.y + EPS;
                    float pb = pbv  + EPS;
                    if (tl < CHUNK - 1) {
                        pv  = *(const float2*)&sm[buf][tl + 1][2 * l];
                        pbv = sm[buf][tl + 1][64];
                    }
                    int t = c * CHUNK + tl;
                    if (t == 0) {
                        if (l == 0) { a0 = pb; a1 = px; }
                    } else {
                        float pa3 = __shfl_up_sync(0xffffffffu, a3, 1);
                        if (l == 0) pa3 = 0.f;
                        float n0 = (a0 + pa3) * pb;                        // s=4l (blank)
                        float n1 = (a1 + a0 + (al1 ? pa3 : 0.f)) * px;     // s=4l+1
                        float n2 = (a2 + a1) * pb;                         // s=4l+2 (blank)
                        float n3 = (a3 + a2 + (al3 ? a1 : 0.f)) * py;      // s=4l+3
                        float n4 = (l == 31) ? (a4 + a3) * pb : 0.f;       // s=128 (blank)
                        a0 = n0; a1 = n1; a2 = n2; a3 = n3; a4 = n4;
                    }
                    // pipelined warp-max + exact 2^k rescale (period 4)
                    int ph = t & 3;
                    if (ph == 0) {
                        r = fmaxf(fmaxf(a0, a1), fmaxf(a2, a3));
                        if (l == 31) r = fmaxf(r, a4);
                        r = fmaxf(r, __shfl_xor_sync(0xffffffffu, r, 1));
                    } else if (ph == 1) {
                        r = fmaxf(r, __shfl_xor_sync(0xffffffffu, r, 2));
                        r = fmaxf(r, __shfl_xor_sync(0xffffffffu, r, 4));
                    } else if (ph == 2) {
                        r = fmaxf(r, __shfl_xor_sync(0xffffffffu, r, 8));
                        r = fmaxf(r, __shfl_xor_sync(0xffffffffu, r, 16));
                    } else {
                        int eb = (__float_as_int(r) >> 23) & 0xff;
                        int se = 254 - eb + BOOST;            // target: max -> 2^BOOST
                        se = se > 254 ? 254 : se;
                        float sc = __int_as_float(se << 23);  // exact 2^(se-127)
                        a0 *= sc; a1 *= sc; a2 *= sc; a3 *= sc; a4 *= sc;
                        esc += 127 - se;
                    }
                }
            }
            __syncthreads();   // b2
        }

        // ll = 64 -> loss from states 128 (a4) and 127 (a3), lane 31
        if (l == 31) {
            float s = a4 + a3;
            out[b] = -(logf(s) + (float)esc * 0.69314718055994531f);
        }
    }
}

extern "C" void kernel_launch(void* const* d_in, const int* in_sizes, int n_in,
                              void* d_out, int out_size) {
    const int*   y_true = (const int*)d_in[0];    // [256, 64] int32
    const float* y_pred = (const float*)d_in[1];  // [256, 512, 1024] float32
    float*       out    = (float*)d_out;          // [256, 1] float32

    ctc_cp_kernel<<<Bv, 256>>>(y_true, y_pred, out);
}

// round 8
// speedup vs baseline: 1.3593x; 1.2352x over previous
#include <cuda_runtime.h>
#include <cstdint>

// Problem shape (fixed by setup_inputs): B=256, T=512, C=1024, L=64, S=129
#define Bv 256
#define Tv 512
#define Cv 1024
#define Lv 64
#define EPS 1e-7f
#define PD 16             // demand-ring depth (steps); 3 LDG/step -> 48 outstanding < 55 cap
#define PFD 64            // L2-prefetch lead (steps); window 256 warps*64*3.5KB ~ 57MB < L2
#define BOOST 100         // rescale target: warp max -> 2^BOOST (underflow margin)

// ---------------------------------------------------------------------------
// Fused CTC forward: one warp per batch row (R3 structure) + L2 line prefetch.
// DRAM fetch granularity is 128B (measured: 472MB moved on 3 different load
// paths), so per row-step ~28 distinct 128B lines are needed. Lane l owns
// line l of each 4KB y_pred row; a 32-bit warp-shared bitmap of touched lines
// predicates ONE prefetch.global.L2 per step, 64 steps ahead. Prefetches have
// no writeback/scoreboard -> unlimited outstanding -> DRAM saturates; the
// demand ring (PD=16, 640cyc lead) then rides L2 hits (~260cyc).
// DP: lane l owns states {4l..4l+3}; lane 31 also owns state 128. Even states
// are blank (no s-2 skip) -> ONE shfl_up per step. Linear-domain recurrence
// with exact power-of-2 rescaling (exponent surgery, warp-max pipelined over
// a 4-step period off the critical path).
// ---------------------------------------------------------------------------
__global__ void __launch_bounds__(32) ctc_pf_kernel(const int* __restrict__ y_true,
                                                    const float* __restrict__ y_pred,
                                                    float* __restrict__ out) {
    int b = blockIdx.x;
    int l = threadIdx.x;

    // labels owned by this lane (constant over t)
    int c0 = y_true[b * Lv + 2 * l];
    int c1 = y_true[b * Lv + 2 * l + 1];
    int cm1 = __shfl_up_sync(0xffffffffu, c1, 1);
    bool al1 = (l > 0) && (c0 != cm1);   // skip into state 4l+1
    bool al3 = (c1 != c0);               // skip into state 4l+3

    // 128B-line bitmap of this row's touched columns (labels + blank)
    unsigned lm = (1u << (c0 >> 5)) | (1u << (c1 >> 5)) | (1u << 31);
#pragma unroll
    for (int o = 16; o; o >>= 1) lm |= __shfl_xor_sync(0xffffffffu, lm, o);
    bool pf_on = (lm >> l) & 1u;

    const float* bp = y_pred + (size_t)b * Tv * Cv;
    const float* p0 = bp + c0;
    const float* p1 = bp + c1;
    const float* pB = bp + (Cv - 1);          // blank = last class (lane-uniform)
    const float* pf = bp + (l << 5);          // lane l -> line l of each row

    // prefetch warmup: rows 0..PFD-1 (covers ring init + first loop iterations)
    if (pf_on) {
#pragma unroll 8
        for (int t = 0; t < PFD; t++)
            asm volatile("prefetch.global.L2 [%0];" :: "l"(pf + (size_t)t * Cv));
    }

    // demand register ring
    float f0[PD], f1[PD], fb[PD];
#pragma unroll
    for (int i = 0; i < PD; i++) {
        f0[i] = p0[i * Cv];
        f1[i] = p1[i * Cv];
        fb[i] = pB[i * Cv];
    }

    float a0 = 0.f, a1 = 0.f, a2 = 0.f, a3 = 0.f, a4 = 0.f;
    float r  = 1.0f;
    int   esc = 0;   // invariant: alpha_true = a * 2^esc  (identical on all lanes)

#pragma unroll 16
    for (int t = 0; t < Tv; t++) {
        int bi = t & (PD - 1);
        float px = f0[bi] + EPS;
        float py = f1[bi] + EPS;
        float pb = fb[bi] + EPS;

        if (t == 0) {
            // alpha0: states 0 (blank) and 1 (label 0) only
            if (l == 0) { a0 = pb; a1 = px; }
        } else {
            float pa3 = __shfl_up_sync(0xffffffffu, a3, 1);
            if (l == 0) pa3 = 0.f;
            float n0 = (a0 + pa3) * pb;                          // s=4l   (blank)
            float n1 = (a1 + a0 + (al1 ? pa3 : 0.f)) * px;       // s=4l+1
            float n2 = (a2 + a1) * pb;                           // s=4l+2 (blank)
            float n3 = (a3 + a2 + (al3 ? a1 : 0.f)) * py;        // s=4l+3
            float n4 = (l == 31) ? (a4 + a3) * pb : 0.f;         // s=128  (blank)
            a0 = n0; a1 = n1; a2 = n2; a3 = n3; a4 = n4;
        }

        // L2 prefetch PFD steps ahead (no writeback -> free MLP)
        int tp = t + PFD;
        if (pf_on && tp < Tv)
            asm volatile("prefetch.global.L2 [%0];" :: "l"(pf + (size_t)tp * Cv));

        // demand prefetch step t+PD (L2 hits in steady state)
        int tn = t + PD;
        if (tn < Tv) {
            f0[bi] = p0[tn * Cv];
            f1[bi] = p1[tn * Cv];
            fb[bi] = pB[tn * Cv];
        }

        // pipelined warp-max + exact 2^k rescale (period 4; off critical path)
        int ph = t & 3;
        if (ph == 0) {
            r = fmaxf(fmaxf(a0, a1), fmaxf(a2, a3));
            if (l == 31) r = fmaxf(r, a4);
            r = fmaxf(r, __shfl_xor_sync(0xffffffffu, r, 1));
        } else if (ph == 1) {
            r = fmaxf(r, __shfl_xor_sync(0xffffffffu, r, 2));
            r = fmaxf(r, __shfl_xor_sync(0xffffffffu, r, 4));
        } else if (ph == 2) {
            r = fmaxf(r, __shfl_xor_sync(0xffffffffu, r, 8));
            r = fmaxf(r, __shfl_xor_sync(0xffffffffu, r, 16));
        } else {
            int eb = (__float_as_int(r) >> 23) & 0xff;   // exponent field of warp max
            int se = 254 - eb + BOOST;                   // target: max -> 2^BOOST
            se = se > 254 ? 254 : se;                    // keep float bits valid
            float sc = __int_as_float(se << 23);         // exact 2^(se-127)
            a0 *= sc; a1 *= sc; a2 *= sc; a3 *= sc; a4 *= sc;
            esc += 127 - se;                             // alpha_true = a * 2^esc
        }
    }

    // ll = 64 for this input set -> loss from states 128 (a4) and 127 (a3), lane 31
    if (l == 31) {
        float s = a4 + a3;
        out[b] = -(logf(s) + (float)esc * 0.69314718055994531f);
    }
}

extern "C" void kernel_launch(void* const* d_in, const int* in_sizes, int n_in,
                              void* d_out, int out_size) {
    const int*   y_true = (const int*)d_in[0];    // [256, 64] int32
    const float* y_pred = (const float*)d_in[1];  // [256, 512, 1024] float32
    float*       out    = (float*)d_out;          // [256, 1] float32

    ctc_pf_kernel<<<Bv, 32>>>(y_true, y_pred, out);
}